// round 8
// baseline (speedup 1.0000x reference)
#include <cuda_runtime.h>
#include <cuda_bf16.h>
#include <cstdint>

// ---------------------------------------------------------------------------
// RNN: out[b,t,:] = sigmoid(x@K + h_{t-1}@Wr),  B=64, T=512, D=H=1024
// Phase 1: xh = x @ kernel  -- double-buffered cp.async TF32 mma GEMM, 2 CTA/SM
// Phase 2: ONE persistent kernel, 64 CTAs, 512 steps.
//   Warp grid 2(M:32 rows)x4(K:256 cols), private cp.async chunk rings.
//   Grid sync via DISTRIBUTED FLAGS, monotonic for the whole launch; flags
//   are reset by a tiny stream-ordered kernel BEFORE the persistent kernel
//   (no in-kernel reset -> no exit race, no replay race).
// ---------------------------------------------------------------------------

#define BATCH 64
#define TSEQ  512
#define DIM   1024

// ---- phase 2 geometry ----
#define NCTA   64
#define NTILE  16
#define BS_STRIDE 1028                // 1024 + 4 (conflict-free)
#define BS_WORDS  (NTILE * BS_STRIDE) // 16448
#define A_STRIDE  68                  // 64 + 4 pad
#define ABUF_WORDS (32 * A_STRIDE)    // chunk buffer: 32 rows x 64 cols
#define A_REGION_WORDS (8 * 2 * ABUF_WORDS)
#define P2_SMEM_BYTES ((BS_WORDS + A_REGION_WORDS) * 4)   // 205,056 B

// ---- phase 1 geometry ----
#define G_BM 128
#define G_BN 128
#define G_BK 32
#define GA_STRIDE 36
#define GB_STRIDE 132
#define G_STAGE_WORDS (G_BM * GA_STRIDE + G_BK * GB_STRIDE)
#define G_SMEM_BYTES  (2 * G_STAGE_WORDS * 4)   // 70,656 B (2 CTAs fit 228KB)

__device__ float g_xh[(size_t)BATCH * TSEQ * DIM];
__device__ unsigned g_flags[NCTA];   // barrier flags; zeroed by reset kernel

__device__ __forceinline__ uint32_t f2tf32(float x) {
    uint32_t r;
    asm("cvt.rna.tf32.f32 %0, %1;" : "=r"(r) : "f"(x));
    return r;
}

__device__ __forceinline__ void mma_tf32(float* d,
                                         uint32_t a0, uint32_t a1, uint32_t a2, uint32_t a3,
                                         uint32_t b0, uint32_t b1) {
    asm volatile(
        "mma.sync.aligned.m16n8k8.row.col.f32.tf32.tf32.f32 "
        "{%0,%1,%2,%3}, {%4,%5,%6,%7}, {%8,%9}, {%0,%1,%2,%3};\n"
        : "+f"(d[0]), "+f"(d[1]), "+f"(d[2]), "+f"(d[3])
        : "r"(a0), "r"(a1), "r"(a2), "r"(a3), "r"(b0), "r"(b1));
}

__device__ __forceinline__ float sigmoidf_fast(float z) {
    return 1.0f / (1.0f + __expf(-z));
}

__device__ __forceinline__ void cp16(uint32_t smem_addr, const void* gsrc) {
    asm volatile("cp.async.cg.shared.global [%0], [%1], 16;\n"
                 :: "r"(smem_addr), "l"(gsrc));
}
__device__ __forceinline__ void cp_commit() {
    asm volatile("cp.async.commit_group;\n" ::: "memory");
}
template <int N>
__device__ __forceinline__ void cp_wait() {
    asm volatile("cp.async.wait_group %0;\n" :: "n"(N) : "memory");
}

// ---------------------------------------------------------------------------
// Flag reset: runs stream-ordered BEFORE the persistent kernel each launch.
// ---------------------------------------------------------------------------
__global__ void reset_flags_kernel() {
    if (threadIdx.x < NCTA) g_flags[threadIdx.x] = 0u;
}

// ---------------------------------------------------------------------------
// Phase 1: xh = X[32768,1024] @ W[1024,1024]  (2 CTAs/SM)
// ---------------------------------------------------------------------------
__global__ __launch_bounds__(256, 2) void gemm_xh_kernel(const float* __restrict__ X,
                                                         const float* __restrict__ W) {
    extern __shared__ uint32_t gsm[];

    const int tid  = threadIdx.x;
    const int lane = tid & 31;
    const int wid  = tid >> 5;
    const int bm   = blockIdx.y * G_BM;
    const int bn   = blockIdx.x * G_BN;
    const int wm   = (wid & 1) * 64;
    const int wn   = (wid >> 1) * 32;
    const int gid  = lane >> 2;
    const int tg   = lane & 3;

    auto As = [&](int s) { return gsm + s * G_STAGE_WORDS; };
    auto Bs = [&](int s) { return gsm + s * G_STAGE_WORDS + G_BM * GA_STRIDE; };

    auto issue = [&](int k0, int s) {
        uint32_t abase = (uint32_t)__cvta_generic_to_shared(As(s));
        uint32_t bbase = (uint32_t)__cvta_generic_to_shared(Bs(s));
        #pragma unroll
        for (int i = 0; i < 4; i++) {
            int idx = tid + i * 256;
            int r = idx >> 3;
            int c = (idx & 7) * 4;
            cp16(abase + (r * GA_STRIDE + c) * 4,
                 X + (size_t)(bm + r) * DIM + k0 + c);
        }
        #pragma unroll
        for (int i = 0; i < 4; i++) {
            int idx = tid + i * 256;
            int r = idx >> 5;
            int c = (idx & 31) * 4;
            cp16(bbase + (r * GB_STRIDE + c) * 4,
                 W + (size_t)(k0 + r) * DIM + bn + c);
        }
        cp_commit();
    };

    float acc[4][4][4];
    #pragma unroll
    for (int mt = 0; mt < 4; mt++)
        #pragma unroll
        for (int nt = 0; nt < 4; nt++)
            #pragma unroll
            for (int i = 0; i < 4; i++) acc[mt][nt][i] = 0.0f;

    issue(0, 0);
    issue(G_BK, 1);

    const int NKITER = DIM / G_BK;
    for (int kb = 0; kb < NKITER; kb++) {
        if (kb < NKITER - 1) cp_wait<1>(); else cp_wait<0>();
        __syncthreads();

        const uint32_t* A = As(kb & 1);
        const uint32_t* B = Bs(kb & 1);

        #pragma unroll
        for (int k8 = 0; k8 < G_BK; k8 += 8) {
            uint32_t a[4][4], b[4][2];
            #pragma unroll
            for (int mt = 0; mt < 4; mt++) {
                int r = (wm + mt * 16 + gid) * GA_STRIDE;
                a[mt][0] = A[r + k8 + tg];
                a[mt][1] = A[r + 8 * GA_STRIDE + k8 + tg];
                a[mt][2] = A[r + k8 + tg + 4];
                a[mt][3] = A[r + 8 * GA_STRIDE + k8 + tg + 4];
            }
            #pragma unroll
            for (int nt = 0; nt < 4; nt++) {
                int c = wn + nt * 8 + gid;
                b[nt][0] = B[(k8 + tg) * GB_STRIDE + c];
                b[nt][1] = B[(k8 + tg + 4) * GB_STRIDE + c];
            }
            #pragma unroll
            for (int mt = 0; mt < 4; mt++)
                #pragma unroll
                for (int nt = 0; nt < 4; nt++)
                    mma_tf32(acc[mt][nt], a[mt][0], a[mt][1], a[mt][2], a[mt][3],
                             b[nt][0], b[nt][1]);
        }
        __syncthreads();
        if (kb + 2 < NKITER) issue((kb + 2) * G_BK, kb & 1);
    }

    #pragma unroll
    for (int mt = 0; mt < 4; mt++) {
        #pragma unroll
        for (int nt = 0; nt < 4; nt++) {
            int r = bm + wm + mt * 16 + gid;
            int c = bn + wn + nt * 8 + tg * 2;
            *(float2*)(&g_xh[(size_t)r * DIM + c]) =
                make_float2(acc[mt][nt][0], acc[mt][nt][1]);
            *(float2*)(&g_xh[(size_t)(r + 8) * DIM + c]) =
                make_float2(acc[mt][nt][2], acc[mt][nt][3]);
        }
    }
}

// ---------------------------------------------------------------------------
// Phase 2: persistent recurrence. 64 CTAs x 256 thr (8 warps).
// Warp w: rows [wm2, wm2+32), K quarter kq=w>>1, all 16 N cols.
// Private double-buffered chunk ring (4 chunks of 32x64).
// Partials -> SMEM scratch (aliases rings) -> flat epilogue.
// Grid sync: monotonic distributed flags (no reset inside the kernel).
// ---------------------------------------------------------------------------
__global__ __launch_bounds__(256, 1) void rnn_persistent(const float* __restrict__ Wr,
                                                         float* __restrict__ OUT) {
    extern __shared__ uint32_t smem[];
    uint32_t* Bsm  = smem;                 // [16][BS_STRIDE] tf32 Wr (transposed)
    uint32_t* Abuf = smem + BS_WORDS;      // 8 warps x 2 bufs x [32][A_STRIDE]
    float*    Scr  = (float*)Abuf;         // reduction scratch (aliases rings)

    const int tid  = threadIdx.x;
    const int lane = tid & 31;
    const int wid  = tid >> 5;
    const int bid  = blockIdx.x;
    const int bn   = bid * NTILE;
    const int wm2  = (wid & 1) * 32;       // M rows base
    const int kq   = wid >> 1;             // K quarter 0..3
    const int kbase = kq * 256;
    const int gid  = lane >> 2;
    const int tg   = lane & 3;

    // Wr slice -> SMEM transposed [n][k], RNA tf32 (once)
    for (int idx = tid; idx < NTILE * DIM; idx += 256) {
        int n = idx & (NTILE - 1);
        int k = idx >> 4;
        Bsm[n * BS_STRIDE + k] = f2tf32(Wr[(size_t)k * DIM + bn + n]);
    }
    __syncthreads();

    const uint32_t* Aw = Abuf + wid * 2 * ABUF_WORDS;
    const uint32_t warp_sb = (uint32_t)__cvta_generic_to_shared(Abuf)
                           + wid * 2 * ABUF_WORDS * 4;

    for (int t = 0; t < TSEQ; t++) {
        float acc[2][2][2][4];   // [chain][mt][nt][frag]
        #pragma unroll
        for (int ch = 0; ch < 2; ch++)
            #pragma unroll
            for (int mt = 0; mt < 2; mt++)
                #pragma unroll
                for (int nt = 0; nt < 2; nt++)
                    #pragma unroll
                    for (int i = 0; i < 4; i++) acc[ch][mt][nt][i] = 0.0f;

        if (t > 0) {
            const float* Hprev = OUT + (size_t)(t - 1) * DIM;

            // issue chunk c (32 rows x 64 floats = 16 cp16/lane) into buf c&1
            auto issue = [&](int c) {
                const int k0 = kbase + c * 64;
                const uint32_t base = warp_sb + (c & 1) * ABUF_WORDS * 4;
                #pragma unroll
                for (int i = 0; i < 16; i++) {
                    int idx = lane + i * 32;
                    int r  = idx >> 4;        // 0..31
                    int c4 = idx & 15;        // 0..15
                    cp16(base + (r * A_STRIDE + c4 * 4) * 4,
                         Hprev + (size_t)(wm2 + r) * (TSEQ * DIM) + k0 + c4 * 4);
                }
                cp_commit();
            };

            issue(0);
            issue(1);

            #pragma unroll
            for (int c = 0; c < 4; c++) {
                if (c < 3) cp_wait<1>(); else cp_wait<0>();
                __syncwarp();

                const uint32_t* Ab = Aw + (c & 1) * ABUF_WORDS;
                const int kb = kbase + c * 64;

                #pragma unroll
                for (int k8i = 0; k8i < 8; k8i++) {
                    const int kk = k8i * 8;
                    const int ch = k8i & 1;
                    uint32_t a[2][4];
                    #pragma unroll
                    for (int mt = 0; mt < 2; mt++) {
                        int lr = (mt * 16 + gid) * A_STRIDE;
                        a[mt][0] = Ab[lr + kk + tg];
                        a[mt][1] = Ab[lr + 8 * A_STRIDE + kk + tg];
                        a[mt][2] = Ab[lr + kk + tg + 4];
                        a[mt][3] = Ab[lr + 8 * A_STRIDE + kk + tg + 4];
                    }
                    #pragma unroll
                    for (int nt = 0; nt < 2; nt++) {
                        int n = nt * 8 + gid;
                        uint32_t b0 = Bsm[n * BS_STRIDE + kb + kk + tg];
                        uint32_t b1 = Bsm[n * BS_STRIDE + kb + kk + tg + 4];
                        #pragma unroll
                        for (int mt = 0; mt < 2; mt++)
                            mma_tf32(acc[ch][mt][nt], a[mt][0], a[mt][1],
                                     a[mt][2], a[mt][3], b0, b1);
                    }
                }
                if (c + 2 < 4) issue(c + 2);
            }
        }

        // fold chains
        float accf[2][2][4];
        #pragma unroll
        for (int mt = 0; mt < 2; mt++)
            #pragma unroll
            for (int nt = 0; nt < 2; nt++)
                #pragma unroll
                for (int i = 0; i < 4; i++)
                    accf[mt][nt][i] = acc[0][mt][nt][i] + acc[1][mt][nt][i];

        // all compute done before scratch (aliases A rings)
        __syncthreads();

        // partial store: P[kq][row 0..63][col 0..15]
        #pragma unroll
        for (int mt = 0; mt < 2; mt++) {
            int rg = wm2 + mt * 16 + gid;
            #pragma unroll
            for (int nt = 0; nt < 2; nt++) {
                int off = kq * 1024 + rg * 16 + nt * 8 + tg * 2;
                *(float2*)&Scr[off]          = make_float2(accf[mt][nt][0], accf[mt][nt][1]);
                *(float2*)&Scr[off + 8 * 16] = make_float2(accf[mt][nt][2], accf[mt][nt][3]);
            }
        }
        __syncthreads();

        // flat epilogue: 256 threads x 4 outputs
        {
            int o   = tid * 4;
            int row = o >> 4;
            int col = o & 15;
            float4 s0 = *(const float4*)&Scr[o];
            float4 s1 = *(const float4*)&Scr[1024 + o];
            float4 s2 = *(const float4*)&Scr[2048 + o];
            float4 s3 = *(const float4*)&Scr[3072 + o];
            float sx = s0.x + s1.x + s2.x + s3.x;
            float sy = s0.y + s1.y + s2.y + s3.y;
            float sz = s0.z + s1.z + s2.z + s3.z;
            float sw = s0.w + s1.w + s2.w + s3.w;
            size_t go = ((size_t)row * TSEQ + t) * DIM + bn + col;
            float4 xh = *(const float4*)&g_xh[go];
            float4 h;
            h.x = sigmoidf_fast(sx + xh.x);
            h.y = sigmoidf_fast(sy + xh.y);
            h.z = sigmoidf_fast(sz + xh.z);
            h.w = sigmoidf_fast(sw + xh.w);
            *(float4*)&OUT[go] = h;
        }

        // ---- distributed-flag grid barrier (monotonic within the launch) ----
        __syncthreads();
        if (tid == 0) {
            asm volatile("st.release.gpu.global.u32 [%0], %1;"
                         :: "l"(&g_flags[bid]), "r"((unsigned)(t + 1)) : "memory");
        }
        {
            const unsigned target = (unsigned)(t + 1);
            int ok;
            do {
                unsigned v = target;
                if (tid < NCTA) {
                    asm volatile("ld.acquire.gpu.global.u32 %0, [%1];"
                                 : "=r"(v) : "l"(&g_flags[tid]) : "memory");
                }
                ok = __syncthreads_and((int)(v >= target));
            } while (!ok);
        }
    }
    // NO in-kernel flag reset: flags stay at TSEQ until the next launch's
    // stream-ordered reset_flags_kernel zeroes them (no exit race).
}

// ---------------------------------------------------------------------------
extern "C" void kernel_launch(void* const* d_in, const int* in_sizes, int n_in,
                              void* d_out, int out_size) {
    const float* x  = (const float*)d_in[0];  // [64, 512, 1024]
    const float* w  = (const float*)d_in[1];  // [1024, 1024]
    const float* wr = (const float*)d_in[2];  // [1024, 1024]
    float* out = (float*)d_out;               // [64, 512, 1024]

    cudaFuncSetAttribute(gemm_xh_kernel,
                         cudaFuncAttributeMaxDynamicSharedMemorySize, G_SMEM_BYTES);
    cudaFuncSetAttribute(rnn_persistent,
                         cudaFuncAttributeMaxDynamicSharedMemorySize, P2_SMEM_BYTES);

    // Reset barrier flags (stream-ordered: prior replay's persistent kernel
    // has fully exited before this runs).
    reset_flags_kernel<<<1, NCTA>>>();

    dim3 grid1(DIM / G_BN, (BATCH * TSEQ) / G_BM);
    gemm_xh_kernel<<<grid1, 256, G_SMEM_BYTES>>>(x, w);

    rnn_persistent<<<NCTA, 256, P2_SMEM_BYTES>>>(wr, out);
}

// round 9
// speedup vs baseline: 1.2150x; 1.2150x over previous
#include <cuda_runtime.h>
#include <cuda_bf16.h>
#include <cstdint>

// ---------------------------------------------------------------------------
// RNN: out[b,t,:] = sigmoid(x@K + h_{t-1}@Wr),  B=64, T=512, D=H=1024
// FUSED single launch, 152 CTAs:
//   bids 0..63   : persistent recurrence (R5-proven: warp-private cp.async
//                  rings, SMEM scratch K-reduction, atomic-counter barrier)
//   bids 64..151 : GEMM worker pool computing xh tiles in t-quarter-major
//                  order, signaling g_qdone[quarter] with release semantics.
// Recurrence waits on quarter q only at steps t = q*128 -> phase 1 is hidden.
// ---------------------------------------------------------------------------

#define BATCH 64
#define TSEQ  512
#define DIM   1024

#define NPERS 64          // persistent (recurrence) CTAs
#define NGEMM 88          // gemm worker CTAs
#define NCTA_TOTAL (NPERS + NGEMM)
#define NTILES 2048       // 256 M-tiles x 8 N-tiles
#define TILES_PER_Q 512   // tiles per t-quarter

// ---- recurrence geometry (R5) ----
#define NTILE  16
#define BS_STRIDE 1028
#define BS_WORDS  (NTILE * BS_STRIDE)
#define A_STRIDE  68
#define ABUF_WORDS (32 * A_STRIDE)
#define FUSED_SMEM_BYTES ((BS_WORDS + 8 * 2 * ABUF_WORDS) * 4)   // 205,056 B

// ---- gemm geometry ----
#define G_BM 128
#define G_BN 128
#define G_BK 32
#define GA_STRIDE 36
#define GB_STRIDE 132
#define G_STAGE_WORDS (G_BM * GA_STRIDE + G_BK * GB_STRIDE)      // 8832 words
// 2 stages = 70,656 B <= FUSED_SMEM_BYTES ✓

__device__ float g_xh[(size_t)BATCH * TSEQ * DIM];
__device__ unsigned g_qdone[4];   // tiles completed per t-quarter
__device__ unsigned g_count;      // barrier arrivals (self-restoring)
__device__ unsigned g_sense;      // barrier sense (self-restoring)

__device__ __forceinline__ uint32_t f2tf32(float x) {
    uint32_t r;
    asm("cvt.rna.tf32.f32 %0, %1;" : "=r"(r) : "f"(x));
    return r;
}

__device__ __forceinline__ void mma_tf32(float* d,
                                         uint32_t a0, uint32_t a1, uint32_t a2, uint32_t a3,
                                         uint32_t b0, uint32_t b1) {
    asm volatile(
        "mma.sync.aligned.m16n8k8.row.col.f32.tf32.tf32.f32 "
        "{%0,%1,%2,%3}, {%4,%5,%6,%7}, {%8,%9}, {%0,%1,%2,%3};\n"
        : "+f"(d[0]), "+f"(d[1]), "+f"(d[2]), "+f"(d[3])
        : "r"(a0), "r"(a1), "r"(a2), "r"(a3), "r"(b0), "r"(b1));
}

__device__ __forceinline__ float sigmoidf_fast(float z) {
    return 1.0f / (1.0f + __expf(-z));
}

__device__ __forceinline__ void cp16(uint32_t smem_addr, const void* gsrc) {
    asm volatile("cp.async.cg.shared.global [%0], [%1], 16;\n"
                 :: "r"(smem_addr), "l"(gsrc));
}
__device__ __forceinline__ void cp_commit() {
    asm volatile("cp.async.commit_group;\n" ::: "memory");
}
template <int N>
__device__ __forceinline__ void cp_wait() {
    asm volatile("cp.async.wait_group %0;\n" :: "n"(N) : "memory");
}

// ---------------------------------------------------------------------------
__global__ void reset_state_kernel() {
    if (threadIdx.x < 4) g_qdone[threadIdx.x] = 0u;
    if (threadIdx.x == 4) g_count = 0u;
    if (threadIdx.x == 5) g_sense = 0u;
}

// ---------------------------------------------------------------------------
// GEMM worker path: loop over xh tiles in t-quarter-major order.
// tile_id = q*512 + b*8 + n : rows [b*512 + q*128, +128) x cols [n*128, +128)
// ---------------------------------------------------------------------------
__device__ void gemm_path(uint32_t* gsm, const float* __restrict__ X,
                          const float* __restrict__ W, int gi) {
    const int tid  = threadIdx.x;
    const int lane = tid & 31;
    const int wid  = tid >> 5;
    const int wm   = (wid & 1) * 64;
    const int wn   = (wid >> 1) * 32;
    const int gid  = lane >> 2;
    const int tg   = lane & 3;

    auto As = [&](int s) { return gsm + s * G_STAGE_WORDS; };
    auto Bs = [&](int s) { return gsm + s * G_STAGE_WORDS + G_BM * GA_STRIDE; };

    for (int tile = gi; tile < NTILES; tile += NGEMM) {
        const int q  = tile >> 9;
        const int j  = tile & 511;
        const int bm = (j >> 3) * TSEQ + q * 128;   // row base in [32768]
        const int bn = (j & 7) * G_BN;

        auto issue = [&](int k0, int s) {
            uint32_t abase = (uint32_t)__cvta_generic_to_shared(As(s));
            uint32_t bbase = (uint32_t)__cvta_generic_to_shared(Bs(s));
            #pragma unroll
            for (int i = 0; i < 4; i++) {
                int idx = tid + i * 256;
                int r = idx >> 3;
                int c = (idx & 7) * 4;
                cp16(abase + (r * GA_STRIDE + c) * 4,
                     X + (size_t)(bm + r) * DIM + k0 + c);
            }
            #pragma unroll
            for (int i = 0; i < 4; i++) {
                int idx = tid + i * 256;
                int r = idx >> 5;
                int c = (idx & 31) * 4;
                cp16(bbase + (r * GB_STRIDE + c) * 4,
                     W + (size_t)(k0 + r) * DIM + bn + c);
            }
            cp_commit();
        };

        float acc[4][4][4];
        #pragma unroll
        for (int mt = 0; mt < 4; mt++)
            #pragma unroll
            for (int nt = 0; nt < 4; nt++)
                #pragma unroll
                for (int i = 0; i < 4; i++) acc[mt][nt][i] = 0.0f;

        issue(0, 0);
        issue(G_BK, 1);

        const int NKITER = DIM / G_BK;
        for (int kb = 0; kb < NKITER; kb++) {
            if (kb < NKITER - 1) cp_wait<1>(); else cp_wait<0>();
            __syncthreads();

            const uint32_t* A = As(kb & 1);
            const uint32_t* B = Bs(kb & 1);

            #pragma unroll
            for (int k8 = 0; k8 < G_BK; k8 += 8) {
                uint32_t a[4][4], b[4][2];
                #pragma unroll
                for (int mt = 0; mt < 4; mt++) {
                    int r = (wm + mt * 16 + gid) * GA_STRIDE;
                    a[mt][0] = A[r + k8 + tg];
                    a[mt][1] = A[r + 8 * GA_STRIDE + k8 + tg];
                    a[mt][2] = A[r + k8 + tg + 4];
                    a[mt][3] = A[r + 8 * GA_STRIDE + k8 + tg + 4];
                }
                #pragma unroll
                for (int nt = 0; nt < 4; nt++) {
                    int c = wn + nt * 8 + gid;
                    b[nt][0] = B[(k8 + tg) * GB_STRIDE + c];
                    b[nt][1] = B[(k8 + tg + 4) * GB_STRIDE + c];
                }
                #pragma unroll
                for (int mt = 0; mt < 4; mt++)
                    #pragma unroll
                    for (int nt = 0; nt < 4; nt++)
                        mma_tf32(acc[mt][nt], a[mt][0], a[mt][1], a[mt][2], a[mt][3],
                                 b[nt][0], b[nt][1]);
            }
            __syncthreads();
            if (kb + 2 < NKITER) issue((kb + 2) * G_BK, kb & 1);
        }

        // epilogue -> g_xh
        #pragma unroll
        for (int mt = 0; mt < 4; mt++) {
            #pragma unroll
            for (int nt = 0; nt < 4; nt++) {
                int r = bm + wm + mt * 16 + gid;
                int c = bn + wn + nt * 8 + tg * 2;
                *(float2*)(&g_xh[(size_t)r * DIM + c]) =
                    make_float2(acc[mt][nt][0], acc[mt][nt][1]);
                *(float2*)(&g_xh[(size_t)(r + 8) * DIM + c]) =
                    make_float2(acc[mt][nt][2], acc[mt][nt][3]);
            }
        }

        // signal: all threads' stores visible, then one release-increment
        __threadfence();
        __syncthreads();
        if (tid == 0) {
            asm volatile("red.release.gpu.global.add.u32 [%0], %1;"
                         :: "l"(&g_qdone[q]), "r"(1u) : "memory");
        }
    }
}

// ---------------------------------------------------------------------------
// Recurrence path (R5-proven). 64 CTAs x 256 thr (8 warps).
// Warp w: rows [(w&1)*32, +32), K quarter w>>1, all 16 N cols.
// Waits for xh quarter q at steps t = q*128.
// ---------------------------------------------------------------------------
__device__ void pers_path(uint32_t* smem, const float* __restrict__ Wr,
                          float* __restrict__ OUT, int bid) {
    uint32_t* Bsm  = smem;
    uint32_t* Abuf = smem + BS_WORDS;
    float*    Scr  = (float*)Abuf;

    const int tid  = threadIdx.x;
    const int lane = tid & 31;
    const int wid  = tid >> 5;
    const int bn   = bid * NTILE;
    const int wm2  = (wid & 1) * 32;
    const int kq   = wid >> 1;
    const int kbase = kq * 256;
    const int gid  = lane >> 2;
    const int tg   = lane & 3;

    for (int idx = tid; idx < NTILE * DIM; idx += 256) {
        int n = idx & (NTILE - 1);
        int k = idx >> 4;
        Bsm[n * BS_STRIDE + k] = f2tf32(Wr[(size_t)k * DIM + bn + n]);
    }
    __syncthreads();

    const uint32_t* Aw = Abuf + wid * 2 * ABUF_WORDS;
    const uint32_t warp_sb = (uint32_t)__cvta_generic_to_shared(Abuf)
                           + wid * 2 * ABUF_WORDS * 4;

    for (int t = 0; t < TSEQ; t++) {
        // wait for xh quarter (only at t = 0, 128, 256, 384)
        if ((t & 127) == 0) {
            if (tid == 0) {
                unsigned v;
                do {
                    asm volatile("ld.acquire.gpu.global.u32 %0, [%1];"
                                 : "=r"(v) : "l"(&g_qdone[t >> 7]) : "memory");
                } while (v < TILES_PER_Q);
            }
            __syncthreads();
        }

        float acc[2][2][2][4];
        #pragma unroll
        for (int ch = 0; ch < 2; ch++)
            #pragma unroll
            for (int mt = 0; mt < 2; mt++)
                #pragma unroll
                for (int nt = 0; nt < 2; nt++)
                    #pragma unroll
                    for (int i = 0; i < 4; i++) acc[ch][mt][nt][i] = 0.0f;

        if (t > 0) {
            const float* Hprev = OUT + (size_t)(t - 1) * DIM;

            auto issue = [&](int c) {
                const int k0 = kbase + c * 64;
                const uint32_t base = warp_sb + (c & 1) * ABUF_WORDS * 4;
                #pragma unroll
                for (int i = 0; i < 16; i++) {
                    int idx = lane + i * 32;
                    int r  = idx >> 4;
                    int c4 = idx & 15;
                    cp16(base + (r * A_STRIDE + c4 * 4) * 4,
                         Hprev + (size_t)(wm2 + r) * (TSEQ * DIM) + k0 + c4 * 4);
                }
                cp_commit();
            };

            issue(0);
            issue(1);

            #pragma unroll
            for (int c = 0; c < 4; c++) {
                if (c < 3) cp_wait<1>(); else cp_wait<0>();
                __syncwarp();

                const uint32_t* Ab = Aw + (c & 1) * ABUF_WORDS;
                const int kb = kbase + c * 64;

                #pragma unroll
                for (int k8i = 0; k8i < 8; k8i++) {
                    const int kk = k8i * 8;
                    const int ch = k8i & 1;
                    uint32_t a[2][4];
                    #pragma unroll
                    for (int mt = 0; mt < 2; mt++) {
                        int lr = (mt * 16 + gid) * A_STRIDE;
                        a[mt][0] = Ab[lr + kk + tg];
                        a[mt][1] = Ab[lr + 8 * A_STRIDE + kk + tg];
                        a[mt][2] = Ab[lr + kk + tg + 4];
                        a[mt][3] = Ab[lr + 8 * A_STRIDE + kk + tg + 4];
                    }
                    #pragma unroll
                    for (int nt = 0; nt < 2; nt++) {
                        int n = nt * 8 + gid;
                        uint32_t b0 = Bsm[n * BS_STRIDE + kb + kk + tg];
                        uint32_t b1 = Bsm[n * BS_STRIDE + kb + kk + tg + 4];
                        #pragma unroll
                        for (int mt = 0; mt < 2; mt++)
                            mma_tf32(acc[ch][mt][nt], a[mt][0], a[mt][1],
                                     a[mt][2], a[mt][3], b0, b1);
                    }
                }
                if (c + 2 < 4) issue(c + 2);
            }
        }

        float accf[2][2][4];
        #pragma unroll
        for (int mt = 0; mt < 2; mt++)
            #pragma unroll
            for (int nt = 0; nt < 2; nt++)
                #pragma unroll
                for (int i = 0; i < 4; i++)
                    accf[mt][nt][i] = acc[0][mt][nt][i] + acc[1][mt][nt][i];

        __syncthreads();

        #pragma unroll
        for (int mt = 0; mt < 2; mt++) {
            int rg = wm2 + mt * 16 + gid;
            #pragma unroll
            for (int nt = 0; nt < 2; nt++) {
                int off = kq * 1024 + rg * 16 + nt * 8 + tg * 2;
                *(float2*)&Scr[off]          = make_float2(accf[mt][nt][0], accf[mt][nt][1]);
                *(float2*)&Scr[off + 8 * 16] = make_float2(accf[mt][nt][2], accf[mt][nt][3]);
            }
        }
        __syncthreads();

        {
            int o   = tid * 4;
            int row = o >> 4;
            int col = o & 15;
            float4 s0 = *(const float4*)&Scr[o];
            float4 s1 = *(const float4*)&Scr[1024 + o];
            float4 s2 = *(const float4*)&Scr[2048 + o];
            float4 s3 = *(const float4*)&Scr[3072 + o];
            float sx = s0.x + s1.x + s2.x + s3.x;
            float sy = s0.y + s1.y + s2.y + s3.y;
            float sz = s0.z + s1.z + s2.z + s3.z;
            float sw = s0.w + s1.w + s2.w + s3.w;
            size_t go = ((size_t)row * TSEQ + t) * DIM + bn + col;
            float4 xh = *(const float4*)&g_xh[go];
            float4 h;
            h.x = sigmoidf_fast(sx + xh.x);
            h.y = sigmoidf_fast(sy + xh.y);
            h.z = sigmoidf_fast(sz + xh.z);
            h.w = sigmoidf_fast(sw + xh.w);
            *(float4*)&OUT[go] = h;
        }

        // atomic-counter grid barrier across the 64 persistent CTAs
        // (sense-reversing; state self-restores after 512 even rounds)
        __syncthreads();
        if (tid == 0) {
            unsigned ns = ((unsigned)t & 1u) ^ 1u;
            unsigned old;
            asm volatile("atom.acq_rel.gpu.global.add.u32 %0, [%1], %2;"
                         : "=r"(old) : "l"(&g_count), "r"(1u) : "memory");
            if (old == NPERS - 1) {
                asm volatile("st.relaxed.gpu.global.u32 [%0], %1;"
                             :: "l"(&g_count), "r"(0u) : "memory");
                asm volatile("st.release.gpu.global.u32 [%0], %1;"
                             :: "l"(&g_sense), "r"(ns) : "memory");
            } else {
                unsigned v;
                do {
                    asm volatile("ld.acquire.gpu.global.u32 %0, [%1];"
                                 : "=r"(v) : "l"(&g_sense) : "memory");
                } while (v != ns);
            }
        }
        __syncthreads();
    }
}

// ---------------------------------------------------------------------------
__global__ __launch_bounds__(256, 1) void fused_rnn(const float* __restrict__ X,
                                                    const float* __restrict__ W,
                                                    const float* __restrict__ Wr,
                                                    float* __restrict__ OUT) {
    extern __shared__ uint32_t smem[];
    const int bid = blockIdx.x;
    if (bid < NPERS) {
        pers_path(smem, Wr, OUT, bid);
    } else {
        gemm_path(smem, X, W, bid - NPERS);
    }
}

// ---------------------------------------------------------------------------
extern "C" void kernel_launch(void* const* d_in, const int* in_sizes, int n_in,
                              void* d_out, int out_size) {
    const float* x  = (const float*)d_in[0];  // [64, 512, 1024]
    const float* w  = (const float*)d_in[1];  // [1024, 1024]
    const float* wr = (const float*)d_in[2];  // [1024, 1024]
    float* out = (float*)d_out;               // [64, 512, 1024]

    cudaFuncSetAttribute(fused_rnn,
                         cudaFuncAttributeMaxDynamicSharedMemorySize,
                         FUSED_SMEM_BYTES);

    // stream-ordered state reset (prior replay fully exited before this runs)
    reset_state_kernel<<<1, 32>>>();

    fused_rnn<<<NCTA_TOTAL, 256, FUSED_SMEM_BYTES>>>(x, w, wr, out);
}

// round 10
// speedup vs baseline: 1.2252x; 1.0084x over previous
#include <cuda_runtime.h>
#include <cuda_bf16.h>
#include <cstdint>

// ---------------------------------------------------------------------------
// RNN: out[b,t,:] = sigmoid(x@K + h_{t-1}@Wr),  B=64, T=512, D=H=1024
// FUSED single launch, 152 CTAs x 512 threads:
//   bids 0..63   : persistent recurrence, 16 warps (4/SMSP for latency hiding)
//                  warp grid 2(M:32 rows) x 8(K:128 cols), private cp rings
//   bids 64..151 : GEMM worker pool (xh tiles, t-quarter-major, release sig)
// ---------------------------------------------------------------------------

#define BATCH 64
#define TSEQ  512
#define DIM   1024

#define NPERS 64
#define NGEMM 88
#define NCTA_TOTAL (NPERS + NGEMM)
#define NTILES 2048
#define TILES_PER_Q 512

// ---- recurrence geometry ----
#define NTILE  16
#define BS_STRIDE 1028
#define BS_WORDS  (NTILE * BS_STRIDE)       // 16448
#define A_STRIDE  36                        // 32 + 4 pad
#define ABUF_WORDS (32 * A_STRIDE)          // 1152: chunk 32 rows x 32 cols
#define A_REGION_WORDS (16 * 2 * ABUF_WORDS)   // 36864
#define FUSED_SMEM_BYTES ((BS_WORDS + A_REGION_WORDS) * 4)   // 213,248 B

// ---- gemm geometry (512 threads: warp grid 4M x 4N, warp tile 32x32) ----
#define G_BM 128
#define G_BN 128
#define G_BK 32
#define GA_STRIDE 36
#define GB_STRIDE 132
#define G_STAGE_WORDS (G_BM * GA_STRIDE + G_BK * GB_STRIDE)   // 8832

__device__ float g_xh[(size_t)BATCH * TSEQ * DIM];
__device__ unsigned g_qdone[4];
__device__ unsigned g_count;
__device__ unsigned g_sense;

__device__ __forceinline__ uint32_t f2tf32(float x) {
    uint32_t r;
    asm("cvt.rna.tf32.f32 %0, %1;" : "=r"(r) : "f"(x));
    return r;
}

__device__ __forceinline__ void mma_tf32(float* d,
                                         uint32_t a0, uint32_t a1, uint32_t a2, uint32_t a3,
                                         uint32_t b0, uint32_t b1) {
    asm volatile(
        "mma.sync.aligned.m16n8k8.row.col.f32.tf32.tf32.f32 "
        "{%0,%1,%2,%3}, {%4,%5,%6,%7}, {%8,%9}, {%0,%1,%2,%3};\n"
        : "+f"(d[0]), "+f"(d[1]), "+f"(d[2]), "+f"(d[3])
        : "r"(a0), "r"(a1), "r"(a2), "r"(a3), "r"(b0), "r"(b1));
}

__device__ __forceinline__ float sigmoidf_fast(float z) {
    return 1.0f / (1.0f + __expf(-z));
}

__device__ __forceinline__ void cp16(uint32_t smem_addr, const void* gsrc) {
    asm volatile("cp.async.cg.shared.global [%0], [%1], 16;\n"
                 :: "r"(smem_addr), "l"(gsrc));
}
__device__ __forceinline__ void cp_commit() {
    asm volatile("cp.async.commit_group;\n" ::: "memory");
}
template <int N>
__device__ __forceinline__ void cp_wait() {
    asm volatile("cp.async.wait_group %0;\n" :: "n"(N) : "memory");
}

// ---------------------------------------------------------------------------
__global__ void reset_state_kernel() {
    if (threadIdx.x < 4) g_qdone[threadIdx.x] = 0u;
    if (threadIdx.x == 4) g_count = 0u;
    if (threadIdx.x == 5) g_sense = 0u;
}

// ---------------------------------------------------------------------------
// GEMM worker path (512 threads). tile = q*512 + b*8 + n.
// ---------------------------------------------------------------------------
__device__ void gemm_path(uint32_t* gsm, const float* __restrict__ X,
                          const float* __restrict__ W, int gi) {
    const int tid  = threadIdx.x;
    const int lane = tid & 31;
    const int wid  = tid >> 5;
    const int wm   = (wid & 3) * 32;
    const int wn   = (wid >> 2) * 32;
    const int gid  = lane >> 2;
    const int tg   = lane & 3;

    auto As = [&](int s) { return gsm + s * G_STAGE_WORDS; };
    auto Bs = [&](int s) { return gsm + s * G_STAGE_WORDS + G_BM * GA_STRIDE; };

    for (int tile = gi; tile < NTILES; tile += NGEMM) {
        const int q  = tile >> 9;
        const int j  = tile & 511;
        const int bm = (j >> 3) * TSEQ + q * 128;
        const int bn = (j & 7) * G_BN;

        auto issue = [&](int k0, int s) {
            uint32_t abase = (uint32_t)__cvta_generic_to_shared(As(s));
            uint32_t bbase = (uint32_t)__cvta_generic_to_shared(Bs(s));
            #pragma unroll
            for (int i = 0; i < 2; i++) {
                int idx = tid + i * 512;
                int r = idx >> 3;
                int c = (idx & 7) * 4;
                cp16(abase + (r * GA_STRIDE + c) * 4,
                     X + (size_t)(bm + r) * DIM + k0 + c);
            }
            #pragma unroll
            for (int i = 0; i < 2; i++) {
                int idx = tid + i * 512;
                int r = idx >> 5;
                int c = (idx & 31) * 4;
                cp16(bbase + (r * GB_STRIDE + c) * 4,
                     W + (size_t)(k0 + r) * DIM + bn + c);
            }
            cp_commit();
        };

        float acc[2][4][4];
        #pragma unroll
        for (int mt = 0; mt < 2; mt++)
            #pragma unroll
            for (int nt = 0; nt < 4; nt++)
                #pragma unroll
                for (int i = 0; i < 4; i++) acc[mt][nt][i] = 0.0f;

        issue(0, 0);
        issue(G_BK, 1);

        const int NKITER = DIM / G_BK;
        for (int kb = 0; kb < NKITER; kb++) {
            if (kb < NKITER - 1) cp_wait<1>(); else cp_wait<0>();
            __syncthreads();

            const uint32_t* A = As(kb & 1);
            const uint32_t* B = Bs(kb & 1);

            #pragma unroll
            for (int k8 = 0; k8 < G_BK; k8 += 8) {
                uint32_t a[2][4], b[4][2];
                #pragma unroll
                for (int mt = 0; mt < 2; mt++) {
                    int r = (wm + mt * 16 + gid) * GA_STRIDE;
                    a[mt][0] = A[r + k8 + tg];
                    a[mt][1] = A[r + 8 * GA_STRIDE + k8 + tg];
                    a[mt][2] = A[r + k8 + tg + 4];
                    a[mt][3] = A[r + 8 * GA_STRIDE + k8 + tg + 4];
                }
                #pragma unroll
                for (int nt = 0; nt < 4; nt++) {
                    int c = wn + nt * 8 + gid;
                    b[nt][0] = B[(k8 + tg) * GB_STRIDE + c];
                    b[nt][1] = B[(k8 + tg + 4) * GB_STRIDE + c];
                }
                #pragma unroll
                for (int mt = 0; mt < 2; mt++)
                    #pragma unroll
                    for (int nt = 0; nt < 4; nt++)
                        mma_tf32(acc[mt][nt], a[mt][0], a[mt][1], a[mt][2], a[mt][3],
                                 b[nt][0], b[nt][1]);
            }
            __syncthreads();
            if (kb + 2 < NKITER) issue((kb + 2) * G_BK, kb & 1);
        }

        #pragma unroll
        for (int mt = 0; mt < 2; mt++) {
            #pragma unroll
            for (int nt = 0; nt < 4; nt++) {
                int r = bm + wm + mt * 16 + gid;
                int c = bn + wn + nt * 8 + tg * 2;
                *(float2*)(&g_xh[(size_t)r * DIM + c]) =
                    make_float2(acc[mt][nt][0], acc[mt][nt][1]);
                *(float2*)(&g_xh[(size_t)(r + 8) * DIM + c]) =
                    make_float2(acc[mt][nt][2], acc[mt][nt][3]);
            }
        }

        __threadfence();
        __syncthreads();
        if (tid == 0) {
            asm volatile("red.release.gpu.global.add.u32 [%0], %1;"
                         :: "l"(&g_qdone[q]), "r"(1u) : "memory");
        }
    }
}

// ---------------------------------------------------------------------------
// Recurrence path: 64 CTAs x 512 thr (16 warps, 4/SMSP).
// Warp w: rows [(w&1)*32, +32), K eighth kq8=w>>1 (128 cols), all 16 N cols.
// Private 2-buffer ring of 32x32 chunks (4 chunks per step).
// 8-way K reduction via aliased SMEM scratch -> flat epilogue.
// ---------------------------------------------------------------------------
__device__ void pers_path(uint32_t* smem, const float* __restrict__ Wr,
                          float* __restrict__ OUT, int bid) {
    uint32_t* Bsm  = smem;
    uint32_t* Abuf = smem + BS_WORDS;
    float*    Scr  = (float*)Abuf;

    const int tid   = threadIdx.x;
    const int lane  = tid & 31;
    const int wid   = tid >> 5;
    const int bn    = bid * NTILE;
    const int wm2   = (wid & 1) * 32;
    const int kq8   = wid >> 1;          // 0..7
    const int kbase = kq8 * 128;
    const int gid   = lane >> 2;
    const int tg    = lane & 3;

    for (int idx = tid; idx < NTILE * DIM; idx += 512) {
        int n = idx & (NTILE - 1);
        int k = idx >> 4;
        Bsm[n * BS_STRIDE + k] = f2tf32(Wr[(size_t)k * DIM + bn + n]);
    }
    __syncthreads();

    const uint32_t* Aw = Abuf + wid * 2 * ABUF_WORDS;
    const uint32_t warp_sb = (uint32_t)__cvta_generic_to_shared(Abuf)
                           + wid * 2 * ABUF_WORDS * 4;

    for (int t = 0; t < TSEQ; t++) {
        if ((t & 127) == 0) {
            if (tid == 0) {
                unsigned v;
                do {
                    asm volatile("ld.acquire.gpu.global.u32 %0, [%1];"
                                 : "=r"(v) : "l"(&g_qdone[t >> 7]) : "memory");
                } while (v < TILES_PER_Q);
            }
            __syncthreads();
        }

        float acc[2][2][2][4];   // [chain][mt][nt][frag]
        #pragma unroll
        for (int ch = 0; ch < 2; ch++)
            #pragma unroll
            for (int mt = 0; mt < 2; mt++)
                #pragma unroll
                for (int nt = 0; nt < 2; nt++)
                    #pragma unroll
                    for (int i = 0; i < 4; i++) acc[ch][mt][nt][i] = 0.0f;

        if (t > 0) {
            const float* Hprev = OUT + (size_t)(t - 1) * DIM;

            // chunk c: 32 rows x 32 cols (4KB) = 8 cp16/lane into buf c&1
            auto issue = [&](int c) {
                const int k0 = kbase + c * 32;
                const uint32_t base = warp_sb + (c & 1) * ABUF_WORDS * 4;
                #pragma unroll
                for (int i = 0; i < 8; i++) {
                    int idx = lane + i * 32;
                    int r  = idx >> 3;        // 0..31
                    int c4 = idx & 7;         // 0..7 (x4 words)
                    cp16(base + (r * A_STRIDE + c4 * 4) * 4,
                         Hprev + (size_t)(wm2 + r) * (TSEQ * DIM) + k0 + c4 * 4);
                }
                cp_commit();
            };

            issue(0);
            issue(1);

            #pragma unroll
            for (int c = 0; c < 4; c++) {
                if (c < 3) cp_wait<1>(); else cp_wait<0>();
                __syncwarp();

                const uint32_t* Ab = Aw + (c & 1) * ABUF_WORDS;
                const int kb = kbase + c * 32;

                #pragma unroll
                for (int k8i = 0; k8i < 4; k8i++) {
                    const int kk = k8i * 8;
                    const int ch = k8i & 1;
                    uint32_t a[2][4];
                    #pragma unroll
                    for (int mt = 0; mt < 2; mt++) {
                        int lr = (mt * 16 + gid) * A_STRIDE;
                        a[mt][0] = Ab[lr + kk + tg];
                        a[mt][1] = Ab[lr + 8 * A_STRIDE + kk + tg];
                        a[mt][2] = Ab[lr + kk + tg + 4];
                        a[mt][3] = Ab[lr + 8 * A_STRIDE + kk + tg + 4];
                    }
                    #pragma unroll
                    for (int nt = 0; nt < 2; nt++) {
                        int n = nt * 8 + gid;
                        uint32_t b0 = Bsm[n * BS_STRIDE + kb + kk + tg];
                        uint32_t b1 = Bsm[n * BS_STRIDE + kb + kk + tg + 4];
                        #pragma unroll
                        for (int mt = 0; mt < 2; mt++)
                            mma_tf32(acc[ch][mt][nt], a[mt][0], a[mt][1],
                                     a[mt][2], a[mt][3], b0, b1);
                    }
                }
                if (c + 2 < 4) issue(c + 2);
            }
        }

        float accf[2][2][4];
        #pragma unroll
        for (int mt = 0; mt < 2; mt++)
            #pragma unroll
            for (int nt = 0; nt < 2; nt++)
                #pragma unroll
                for (int i = 0; i < 4; i++)
                    accf[mt][nt][i] = acc[0][mt][nt][i] + acc[1][mt][nt][i];

        __syncthreads();   // compute done before scratch aliases rings

        // partial store: P[kq8][row 0..63][col 0..15]
        #pragma unroll
        for (int mt = 0; mt < 2; mt++) {
            int rg = wm2 + mt * 16 + gid;
            #pragma unroll
            for (int nt = 0; nt < 2; nt++) {
                int off = kq8 * 1024 + rg * 16 + nt * 8 + tg * 2;
                *(float2*)&Scr[off]          = make_float2(accf[mt][nt][0], accf[mt][nt][1]);
                *(float2*)&Scr[off + 8 * 16] = make_float2(accf[mt][nt][2], accf[mt][nt][3]);
            }
        }
        __syncthreads();

        // flat epilogue: 512 threads x 2 outputs
        {
            int o   = tid * 2;
            int row = o >> 4;
            int col = o & 15;
            float sx = 0.0f, sy = 0.0f;
            #pragma unroll
            for (int p = 0; p < 8; p++) {
                float2 s = *(const float2*)&Scr[p * 1024 + o];
                sx += s.x; sy += s.y;
            }
            size_t go = ((size_t)row * TSEQ + t) * DIM + bn + col;
            float2 xh = *(const float2*)&g_xh[go];
            float2 h = make_float2(sigmoidf_fast(sx + xh.x),
                                   sigmoidf_fast(sy + xh.y));
            *(float2*)&OUT[go] = h;
        }

        // atomic-counter grid barrier across 64 persistent CTAs
        __syncthreads();
        if (tid == 0) {
            unsigned ns = ((unsigned)t & 1u) ^ 1u;
            unsigned old;
            asm volatile("atom.acq_rel.gpu.global.add.u32 %0, [%1], %2;"
                         : "=r"(old) : "l"(&g_count), "r"(1u) : "memory");
            if (old == NPERS - 1) {
                asm volatile("st.relaxed.gpu.global.u32 [%0], %1;"
                             :: "l"(&g_count), "r"(0u) : "memory");
                asm volatile("st.release.gpu.global.u32 [%0], %1;"
                             :: "l"(&g_sense), "r"(ns) : "memory");
            } else {
                unsigned v;
                do {
                    asm volatile("ld.acquire.gpu.global.u32 %0, [%1];"
                                 : "=r"(v) : "l"(&g_sense) : "memory");
                } while (v != ns);
            }
        }
        __syncthreads();
    }
}

// ---------------------------------------------------------------------------
__global__ __launch_bounds__(512, 1) void fused_rnn(const float* __restrict__ X,
                                                    const float* __restrict__ W,
                                                    const float* __restrict__ Wr,
                                                    float* __restrict__ OUT) {
    extern __shared__ uint32_t smem[];
    const int bid = blockIdx.x;
    if (bid < NPERS) {
        pers_path(smem, Wr, OUT, bid);
    } else {
        gemm_path(smem, X, W, bid - NPERS);
    }
}

// ---------------------------------------------------------------------------
extern "C" void kernel_launch(void* const* d_in, const int* in_sizes, int n_in,
                              void* d_out, int out_size) {
    const float* x  = (const float*)d_in[0];  // [64, 512, 1024]
    const float* w  = (const float*)d_in[1];  // [1024, 1024]
    const float* wr = (const float*)d_in[2];  // [1024, 1024]
    float* out = (float*)d_out;               // [64, 512, 1024]

    cudaFuncSetAttribute(fused_rnn,
                         cudaFuncAttributeMaxDynamicSharedMemorySize,
                         FUSED_SMEM_BYTES);

    reset_state_kernel<<<1, 32>>>();
    fused_rnn<<<NCTA_TOTAL, 512, FUSED_SMEM_BYTES>>>(x, w, wr, out);
}